// round 10
// baseline (speedup 1.0000x reference)
#include <cuda_runtime.h>
#include <cstdint>
#include <cstddef>

// Dims fixed: B=32, S=512, H=1024, fp32.
#define Bb   32
#define Ss   512
#define Hh   1024
#define NCTA 128
#define NTHR 256
#define RPAD 1028    // padded SMEM row stride (floats)
#define NP   16      // weight prefetch depth (float4 ring => 16 LDGs in flight)

// ---- device scratch (allocation-free rule: __device__ globals) -------------
// Blocked-transposed weights: WT[m][kq][c][j] = W_m[c][4*kq+j], m in {hb,r,b}.
// float4 index = (m*256 + kq)*1024 + c. 12 MB total (L2-resident).
__device__ __align__(16) float4 g_WT4[3 * 256 * 1024];
__device__ __align__(16) float g_Bi[(size_t)Ss * Bb * Hh]; // tanh(x_t W_b^T + b_b), [t][b][h]
__device__ __align__(16) float g_h [Bb * Hh];
__device__ __align__(16) float g_hi[Bb * Hh];
__device__ __align__(16) float g_ri[Bb * Hh];
__device__ __align__(128) unsigned g_arrive;
__device__ __align__(128) unsigned g_release;

__global__ void init_kernel() {
    int i = blockIdx.x * blockDim.x + threadIdx.x;
    if (i < Bb * Hh) g_h[i] = 0.0f;
    if (i == 0) { g_arrive = 0u; g_release = 0u; }
}

// ---------------------------------------------------------------------------
// XLA EmitFastTanh, FMA variant (verified bit-exact in R8/R9).
__device__ __forceinline__ float xla_tanh(float x) {
    float z = fminf(x, 7.99881172180175781f);
    z = fmaxf(z, -7.99881172180175781f);
    float x2 = __fmul_rn(z, z);
    float p = __fmaf_rn(x2, -2.76076847742355e-16f, 2.00018790482477e-13f);
    p = __fmaf_rn(x2, p, -8.60467152213735e-11f);
    p = __fmaf_rn(x2, p,  5.12229709037114e-08f);
    p = __fmaf_rn(x2, p,  1.48572235717979e-05f);
    p = __fmaf_rn(x2, p,  6.37261928875436e-04f);
    p = __fmaf_rn(x2, p,  4.89352455891786e-03f);
    p = __fmul_rn(z, p);
    float q = __fmaf_rn(x2, 1.19825839466702e-06f, 1.18534705686654e-04f);
    q = __fmaf_rn(x2, q, 2.26843463243900e-03f);
    q = __fmaf_rn(x2, q, 4.89352518554385e-03f);
    return (fabsf(x) < 0.0004f) ? x : __fdiv_rn(p, q);
}

// ---------------------------------------------------------------------------
// Weight transpose into k-quad-blocked layout. Pure copy (bit-free).
__global__ void transpose_kernel(const float* __restrict__ Whb,
                                 const float* __restrict__ Wr,
                                 const float* __restrict__ Wb) {
    int i = blockIdx.x * blockDim.x + threadIdx.x;   // 0 .. 3*262144-1
    if (i >= 3 * 262144) return;
    int m  = i >> 18;
    int r  = i & 262143;
    int kq = r >> 10;
    int c  = r & 1023;
    const float* src = (m == 0) ? Whb : (m == 1) ? Wr : Wb;
    g_WT4[i] = ((const float4*)src)[c * 256 + kq];
}

// ---------------------------------------------------------------------------
// Bi precompute (verified bit order; at the fp32 FMA roofline ~0.93 ms).
__global__ __launch_bounds__(NTHR, 1) void bi_kernel(
    const float* __restrict__ x, const float* __restrict__ bbias)
{
    __shared__ float xs[Bb][128];
    const int tid = threadIdx.x;
    const int t   = blockIdx.y;
    const int c   = blockIdx.x * NTHR + tid;
    const float4* wt = g_WT4 + 2 * 262144 + c;   // W_b slice, stride 1024 per kq

    float acc[Bb];
    #pragma unroll
    for (int b = 0; b < Bb; b++) acc[b] = 0.0f;

    for (int kp = 0; kp < 8; kp++) {             // 8 panels of 128 k
        __syncthreads();
        #pragma unroll
        for (int j = 0; j < 4; j++) {
            int i  = tid + j * NTHR;             // 0..1023 float4s
            int b  = i >> 5;
            int kl = i & 31;
            ((float4*)&xs[b][0])[kl] =
                *(const float4*)(x + ((size_t)b * Ss + t) * Hh + kp * 128 + kl * 4);
        }
        __syncthreads();
        #pragma unroll 1
        for (int kl = 0; kl < 32; kl++) {
            float4 w = wt[(kp * 32 + kl) * 1024];
            #pragma unroll
            for (int b = 0; b < Bb; b++) {
                float4 a = *(const float4*)&xs[b][kl * 4];
                acc[b] = __fmaf_rn(a.x, w.x, acc[b]);
                acc[b] = __fmaf_rn(a.y, w.y, acc[b]);
                acc[b] = __fmaf_rn(a.z, w.z, acc[b]);
                acc[b] = __fmaf_rn(a.w, w.w, acc[b]);
            }
        }
    }

    float bias = bbias[c];
    #pragma unroll
    for (int b = 0; b < Bb; b++)
        g_Bi[((size_t)t * Bb + b) * Hh + c] = xla_tanh(__fadd_rn(acc[b], bias));
}

// ---------------------------------------------------------------------------
// Grid barrier, contention-split: arrivals bump a monotonic counter; the LAST
// arriver publishes epoch to g_release (st.release); everyone read-polls the
// release word (no atomic contention on the poll path).
__device__ __forceinline__ void gsync(unsigned* epoch) {
    unsigned e = ++(*epoch);
    __syncthreads();
    if (threadIdx.x == 0) {
        __threadfence();
        unsigned a = atomicAdd(&g_arrive, 1u);
        if (a == e * NCTA - 1u) {
            asm volatile("st.release.gpu.u32 [%0], %1;" :: "l"(&g_release), "r"(e));
        }
        unsigned v;
        do {
            asm volatile("ld.acquire.gpu.u32 %0, [%1];" : "=r"(v) : "l"(&g_release));
        } while (v < e);
    }
    __syncthreads();
}

// ---------------------------------------------------------------------------
// Canonical dot with a 16-deep software-pipelined weight prefetch ring.
// Accumulation is the SAME single ascending-k fma chain (bit-exact); only the
// load schedule changes. Weight LDG: 8 distinct float4/warp (4-way dup) = one
// 128B line. Activation: LDS.128 broadcast from padded SMEM.
__device__ __forceinline__ float dot_pipe(const float4* __restrict__ wt,
                                          const float* __restrict__ sa) {
    float4 wbuf[NP];
    #pragma unroll
    for (int i = 0; i < NP; i++) wbuf[i] = wt[i * 1024];

    float acc = 0.0f;
    #pragma unroll 16
    for (int kq = 0; kq < 256; kq++) {
        float4 w = wbuf[kq & (NP - 1)];
        if (kq < 256 - NP) wbuf[kq & (NP - 1)] = wt[(kq + NP) * 1024];
        float4 a = *(const float4*)(sa + kq * 4);
        acc = __fmaf_rn(a.x, w.x, acc);
        acc = __fmaf_rn(a.y, w.y, acc);
        acc = __fmaf_rn(a.z, w.z, acc);
        acc = __fmaf_rn(a.w, w.w, acc);
    }
    return acc;
}

// Stage 8 rows (b0..b0+7) of a [32][1024] global vector into padded SMEM.
__device__ __forceinline__ void stage8(float* __restrict__ s,
                                       const float* __restrict__ src) {
    int tid = threadIdx.x;
    #pragma unroll
    for (int j = 0; j < 8; j++) {
        int i  = tid + j * NTHR;          // 0..2047 float4s
        int r  = i >> 8;
        int kq = i & 255;
        *(float4*)(s + r * RPAD + kq * 4) = ((const float4*)src)[r * 256 + kq];
    }
}

// Stage fl(ri + pe): single rounded add per element (exactly the reference's
// elementwise (ri + p_t)); subsequent dot chain order untouched => bit-exact.
__device__ __forceinline__ void stage8_add(float* __restrict__ s,
                                           const float* __restrict__ r0,
                                           const float* __restrict__ pe,
                                           int b0, int t) {
    int tid = threadIdx.x;
    #pragma unroll
    for (int j = 0; j < 8; j++) {
        int i  = tid + j * NTHR;
        int r  = i >> 8;
        int kq = i & 255;
        float4 a = ((const float4*)r0)[r * 256 + kq];
        float4 q = *(const float4*)(pe + ((size_t)(b0 + r) * Ss + t) * Hh + kq * 4);
        float4 v;
        v.x = __fadd_rn(a.x, q.x); v.y = __fadd_rn(a.y, q.y);
        v.z = __fadd_rn(a.z, q.z); v.w = __fadd_rn(a.w, q.w);
        *(float4*)(s + r * RPAD + kq * 4) = v;
    }
}

// ---------------------------------------------------------------------------
// Sequential recurrence. 128 CTAs x 256 threads; CTA = 32 c x 8 b.
// Warp = 8 c x 4 b; 2 warps/SMSP interleave the 4-cyc FMA chain onto rt=2.
__global__ __launch_bounds__(NTHR, 1) void seq_kernel(
    const float* __restrict__ pe,
    const float* __restrict__ bb, const float* __restrict__ bhb,
    const float* __restrict__ br,
    float* __restrict__ out)
{
    __shared__ float s_act[8 * RPAD];

    const int tid  = threadIdx.x;
    const int lane = tid & 31;
    const int w    = tid >> 5;
    const int cl   = lane >> 2;               // 0..7
    const int bl   = lane & 3;                // 0..3
    const int c    = (blockIdx.x & 31) * 32 + (w & 3) * 8 + cl;
    const int rl   = (w >> 2) * 4 + bl;       // local b row 0..7
    const int b0   = (blockIdx.x >> 5) * 8;
    const int b    = b0 + rl;
    const int o    = b * Hh + c;

    const float4* wt_hb = g_WT4 + 0 * 262144 + c;
    const float4* wt_r  = g_WT4 + 1 * 262144 + c;
    const float4* wt_b  = g_WT4 + 2 * 262144 + c;
    const float bias_hb = bhb[c];
    const float bias_r  = br[c];
    const float bias_b  = bb[c];
    const float* sa     = s_act + rl * RPAD;

    unsigned epoch = 0u;
    float hi = 0.0f;

    #pragma unroll 1
    for (int t = 0; t < Ss; t++) {
        // sub 1: hi = tanh(h @ W_hb^T + b_hb) + bi[t]
        stage8(s_act, g_h + (size_t)b0 * Hh);
        float bi_v = g_Bi[((size_t)t * Bb + b) * Hh + c];   // independent, early
        __syncthreads();
        float z = dot_pipe(wt_hb, sa);
        hi = __fadd_rn(xla_tanh(__fadd_rn(z, bias_hb)), bi_v);
        g_hi[o] = hi;
        gsync(&epoch);

        // sub 2: ri = tanh(hi @ W_r^T + b_r)
        stage8(s_act, g_hi + (size_t)b0 * Hh);
        __syncthreads();
        z = dot_pipe(wt_r, sa);
        g_ri[o] = xla_tanh(__fadd_rn(z, bias_r));
        gsync(&epoch);

        // sub 3: h = hi + tanh((ri + p_t) @ W_b^T + b_b)
        stage8_add(s_act, g_ri + (size_t)b0 * Hh, pe, b0, t);
        __syncthreads();
        z = dot_pipe(wt_b, sa);
        float hn = __fadd_rn(hi, xla_tanh(__fadd_rn(z, bias_b)));
        g_h[o] = hn;
        if (t == Ss - 1) out[o] = hn;
        gsync(&epoch);
    }
}

// ---------------------------------------------------------------------------
extern "C" void kernel_launch(void* const* d_in, const int* in_sizes, int n_in,
                              void* d_out, int out_size) {
    const float* x   = (const float*)d_in[0];
    const float* pe  = (const float*)d_in[1];
    const float* Wb  = (const float*)d_in[2];
    const float* bb  = (const float*)d_in[3];
    const float* Whb = (const float*)d_in[4];
    const float* bhb = (const float*)d_in[5];
    const float* Wr  = (const float*)d_in[6];
    const float* br  = (const float*)d_in[7];
    float* out = (float*)d_out;

    init_kernel<<<(Bb * Hh + 255) / 256, 256>>>();
    transpose_kernel<<<(3 * 262144 + 255) / 256, 256>>>(Whb, Wr, Wb);
    bi_kernel<<<dim3(Hh / NTHR, Ss), NTHR>>>(x, bb);
    seq_kernel<<<NCTA, NTHR>>>(pe, bb, bhb, br, out);
}

// round 13
// speedup vs baseline: 1.0794x; 1.0794x over previous
#include <cuda_runtime.h>
#include <cstdint>
#include <cstddef>

// Dims fixed: B=32, S=512, H=1024, fp32.
#define Bb   32
#define Ss   512
#define Hh   1024
#define NCTA 128
#define NTHR 256
#define RPAD 1028    // padded SMEM act row stride (floats): conflict-free LDS.128
// dynamic smem: weights 3*8*1024 floats (96KB) + acts 32*RPAD floats (128.5KB)
#define W_F4   (3 * 8 * 256)            // 6144 float4 of weights
#define SMEM_DYN ((3 * 8 * 1024 + Bb * RPAD) * 4)   // 229,888 B

// ---- device scratch (allocation-free rule: __device__ globals) -------------
// k-major transposed Wb for bi_kernel only: g_WT4[kq][c] (float4), 4MB.
__device__ __align__(16) float4 g_WT4[256 * 1024];
__device__ __align__(16) float g_Bi[(size_t)Ss * Bb * Hh]; // tanh(x_t W_b^T + b_b), [t][b][h]
__device__ __align__(16) float g_h [Bb * Hh];
__device__ __align__(16) float g_hi[Bb * Hh];
__device__ __align__(16) float g_ri[Bb * Hh];
__device__ __align__(128) unsigned g_arrive;
__device__ __align__(128) unsigned g_release;

__global__ void init_kernel() {
    int i = blockIdx.x * blockDim.x + threadIdx.x;
    if (i < Bb * Hh) g_h[i] = 0.0f;
    if (i == 0) { g_arrive = 0u; g_release = 0u; }
}

// ---------------------------------------------------------------------------
// XLA EmitFastTanh, FMA variant (verified bit-exact R8-R10).
__device__ __forceinline__ float xla_tanh(float x) {
    float z = fminf(x, 7.99881172180175781f);
    z = fmaxf(z, -7.99881172180175781f);
    float x2 = __fmul_rn(z, z);
    float p = __fmaf_rn(x2, -2.76076847742355e-16f, 2.00018790482477e-13f);
    p = __fmaf_rn(x2, p, -8.60467152213735e-11f);
    p = __fmaf_rn(x2, p,  5.12229709037114e-08f);
    p = __fmaf_rn(x2, p,  1.48572235717979e-05f);
    p = __fmaf_rn(x2, p,  6.37261928875436e-04f);
    p = __fmaf_rn(x2, p,  4.89352455891786e-03f);
    p = __fmul_rn(z, p);
    float q = __fmaf_rn(x2, 1.19825839466702e-06f, 1.18534705686654e-04f);
    q = __fmaf_rn(x2, q, 2.26843463243900e-03f);
    q = __fmaf_rn(x2, q, 4.89352518554385e-03f);
    return (fabsf(x) < 0.0004f) ? x : __fdiv_rn(p, q);
}

// ---------------------------------------------------------------------------
// Wb transpose into [kq][c] layout for bi_kernel. Pure copy (bit-free).
__global__ void transpose_kernel(const float* __restrict__ Wb) {
    int i = blockIdx.x * blockDim.x + threadIdx.x;   // 0 .. 262143
    if (i >= 262144) return;
    int kq = i >> 10;
    int c  = i & 1023;
    g_WT4[i] = ((const float4*)Wb)[(size_t)c * 256 + kq];
}

// ---------------------------------------------------------------------------
// Bi precompute (verified bit order R8-R10; fp32-FMA-roofline-bound ~0.95 ms).
__global__ __launch_bounds__(NTHR, 1) void bi_kernel(
    const float* __restrict__ x, const float* __restrict__ bbias)
{
    __shared__ float xs[Bb][128];
    const int tid = threadIdx.x;
    const int t   = blockIdx.y;
    const int c   = blockIdx.x * NTHR + tid;
    const float4* wt = g_WT4 + c;                // stride 1024 float4 per kq

    float acc[Bb];
    #pragma unroll
    for (int b = 0; b < Bb; b++) acc[b] = 0.0f;

    for (int kp = 0; kp < 8; kp++) {             // 8 panels of 128 k
        __syncthreads();
        #pragma unroll
        for (int j = 0; j < 4; j++) {
            int i  = tid + j * NTHR;             // 0..1023 float4s
            int b  = i >> 5;
            int kl = i & 31;
            ((float4*)&xs[b][0])[kl] =
                *(const float4*)(x + ((size_t)b * Ss + t) * Hh + kp * 128 + kl * 4);
        }
        __syncthreads();
        #pragma unroll 1
        for (int kl = 0; kl < 32; kl++) {
            float4 w = wt[(kp * 32 + kl) * 1024];
            #pragma unroll
            for (int b = 0; b < Bb; b++) {
                float4 a = *(const float4*)&xs[b][kl * 4];
                acc[b] = __fmaf_rn(a.x, w.x, acc[b]);
                acc[b] = __fmaf_rn(a.y, w.y, acc[b]);
                acc[b] = __fmaf_rn(a.z, w.z, acc[b]);
                acc[b] = __fmaf_rn(a.w, w.w, acc[b]);
            }
        }
    }

    float bias = bbias[c];
    #pragma unroll
    for (int b = 0; b < Bb; b++)
        g_Bi[((size_t)t * Bb + b) * Hh + c] = xla_tanh(__fadd_rn(acc[b], bias));
}

// ---------------------------------------------------------------------------
// Grid barrier (contention-split; verified R10).
__device__ __forceinline__ void gsync(unsigned* epoch) {
    unsigned e = ++(*epoch);
    __syncthreads();
    if (threadIdx.x == 0) {
        __threadfence();
        unsigned a = atomicAdd(&g_arrive, 1u);
        if (a == e * NCTA - 1u) {
            asm volatile("st.release.gpu.u32 [%0], %1;" :: "l"(&g_release), "r"(e));
        }
        unsigned v;
        do {
            asm volatile("ld.acquire.gpu.u32 %0, [%1];" : "=r"(v) : "l"(&g_release));
        } while (v < e);
    }
    __syncthreads();
}

// ---------------------------------------------------------------------------
// Canonical dot from SMEM-resident weights + SMEM-staged activation row:
// same single ascending-k fma chain (bit-exact, frozen since R8).
// Weight LDS: 8 distinct float4 (consecutive) x 4-lane dup = 128B broadcast.
// Act LDS: 4 distinct rows x 8-dup, padded stride => conflict-free.
__device__ __forceinline__ float dot_sw(const float4* __restrict__ wp,
                                        const float4* __restrict__ ap) {
    float acc = 0.0f;
    #pragma unroll 8
    for (int kq = 0; kq < 256; kq++) {
        float4 w = wp[kq * 8];
        float4 a = ap[kq];
        acc = __fmaf_rn(a.x, w.x, acc);
        acc = __fmaf_rn(a.y, w.y, acc);
        acc = __fmaf_rn(a.z, w.z, acc);
        acc = __fmaf_rn(a.w, w.w, acc);
    }
    return acc;
}

// Stage all 32 rows of a [32][1024] global vector into padded SMEM.
// Thread tid stages column-quad tid of row j (j = 0..31): LDG.128 coalesced,
// STS conflict-free.
__device__ __forceinline__ void stage32(float* __restrict__ s,
                                        const float* __restrict__ src) {
    int tid = threadIdx.x;
    #pragma unroll
    for (int j = 0; j < 32; j++) {
        *(float4*)(s + j * RPAD + tid * 4) = ((const float4*)src)[j * 256 + tid];
    }
}

// Stage fl(ri + pe): single rounded add per element (the reference's literal
// elementwise (ri + p_t)); dot chain order untouched => bit-exact.
__device__ __forceinline__ void stage32_add(float* __restrict__ s,
                                            const float* __restrict__ r0,
                                            const float* __restrict__ pe,
                                            int t) {
    int tid = threadIdx.x;
    #pragma unroll
    for (int j = 0; j < 32; j++) {
        float4 a = ((const float4*)r0)[j * 256 + tid];
        float4 q = *(const float4*)(pe + ((size_t)j * Ss + t) * Hh + tid * 4);
        float4 v;
        v.x = __fadd_rn(a.x, q.x); v.y = __fadd_rn(a.y, q.y);
        v.z = __fadd_rn(a.z, q.z); v.w = __fadd_rn(a.w, q.w);
        *(float4*)(s + j * RPAD + tid * 4) = v;
    }
}

// ---------------------------------------------------------------------------
// Sequential recurrence, weight-stationary tiling. CTA cb owns columns
// [cb*8, cb*8+8) x ALL 32 batch rows (256 outputs, 1 thread each).
// Warp w: rows 4w..4w+3 (bl = lane&3), cols c0..c0+7 (cl = lane>>2).
// Weights (96KB) loaded to SMEM once; acts staged per sub-step (128KB L2
// broadcast). No global weight traffic in the mainloop at all.
__global__ __launch_bounds__(NTHR, 1) void seq_kernel(
    const float* __restrict__ pe,
    const float* __restrict__ Whb, const float* __restrict__ Wr,
    const float* __restrict__ Wb,
    const float* __restrict__ bb,  const float* __restrict__ bhb,
    const float* __restrict__ br,
    float* __restrict__ out)
{
    extern __shared__ float smem[];
    float4* w_s4  = (float4*)smem;            // [3][256][8] float4 = 96KB
    float*  s_act = smem + 3 * 8 * 1024;      // [32][RPAD]

    const int tid  = threadIdx.x;
    const int lane = tid & 31;
    const int w    = tid >> 5;
    const int cb   = blockIdx.x;
    const int c0   = cb * 8;
    const int cl   = lane >> 2;               // 0..7
    const int bl   = lane & 3;                // 0..3
    const int rl   = w * 4 + bl;              // batch row 0..31
    const int c    = c0 + cl;
    const int o    = rl * Hh + c;

    // prologue: load this CTA's 8 columns of all three weight matrices.
    // idx -> (m, kq, cl2) with cl2 fastest => STS coalesced & conflict-free.
    for (int idx = tid; idx < W_F4; idx += NTHR) {
        int m   = idx >> 11;
        int kq  = (idx >> 3) & 255;
        int cl2 = idx & 7;
        const float* Wm = (m == 0) ? Whb : (m == 1) ? Wr : Wb;
        w_s4[idx] = ((const float4*)Wm)[(size_t)(c0 + cl2) * 256 + kq];
    }
    __syncthreads();

    const float4* wp_hb = w_s4 + 0 * 2048 + cl;
    const float4* wp_r  = w_s4 + 1 * 2048 + cl;
    const float4* wp_b  = w_s4 + 2 * 2048 + cl;
    const float4* ap    = (const float4*)(s_act + rl * RPAD);

    const float bias_hb = bhb[c];
    const float bias_r  = br[c];
    const float bias_b  = bb[c];

    unsigned epoch = 0u;
    float hi = 0.0f;

    #pragma unroll 1
    for (int t = 0; t < Ss; t++) {
        // sub 1: hi = tanh(h @ W_hb^T + b_hb) + bi[t]
        stage32(s_act, g_h);
        float bi_v = g_Bi[((size_t)t * Bb + rl) * Hh + c];
        __syncthreads();
        float z = dot_sw(wp_hb, ap);
        hi = __fadd_rn(xla_tanh(__fadd_rn(z, bias_hb)), bi_v);
        g_hi[o] = hi;
        gsync(&epoch);

        // sub 2: ri = tanh(hi @ W_r^T + b_r)
        stage32(s_act, g_hi);
        __syncthreads();
        z = dot_sw(wp_r, ap);
        g_ri[o] = xla_tanh(__fadd_rn(z, bias_r));
        gsync(&epoch);

        // sub 3: h = hi + tanh((ri + p_t) @ W_b^T + b_b)
        stage32_add(s_act, g_ri, pe, t);
        __syncthreads();
        z = dot_sw(wp_b, ap);
        float hn = __fadd_rn(hi, xla_tanh(__fadd_rn(z, bias_b)));
        g_h[o] = hn;
        if (t == Ss - 1) out[o] = hn;
        gsync(&epoch);
    }
}

// ---------------------------------------------------------------------------
extern "C" void kernel_launch(void* const* d_in, const int* in_sizes, int n_in,
                              void* d_out, int out_size) {
    const float* x   = (const float*)d_in[0];
    const float* pe  = (const float*)d_in[1];
    const float* Wb  = (const float*)d_in[2];
    const float* bb  = (const float*)d_in[3];
    const float* Whb = (const float*)d_in[4];
    const float* bhb = (const float*)d_in[5];
    const float* Wr  = (const float*)d_in[6];
    const float* br  = (const float*)d_in[7];
    float* out = (float*)d_out;

    cudaFuncSetAttribute(seq_kernel, cudaFuncAttributeMaxDynamicSharedMemorySize,
                         SMEM_DYN);

    init_kernel<<<(Bb * Hh + 255) / 256, 256>>>();
    transpose_kernel<<<(262144 + 255) / 256, 256>>>(Wb);
    bi_kernel<<<dim3(Hh / NTHR, Ss), NTHR>>>(x, bb);
    seq_kernel<<<NCTA, NTHR, SMEM_DYN>>>(pe, Whb, Wr, Wb, bb, bhb, br, out);
}

// round 14
// speedup vs baseline: 1.1066x; 1.0252x over previous
#include <cuda_runtime.h>
#include <cstdint>
#include <cstddef>

// Dims fixed: B=32, S=512, H=1024, fp32.
#define Bb   32
#define Ss   512
#define Hh   1024
#define NCTA 128
#define NTHR 256     // bi_kernel threads
#define NTS  128     // seq_kernel threads (2 outputs per thread)
#define RPAD 1028    // padded SMEM act row stride (floats): conflict-free LDS.128
#define W_F4   (3 * 8 * 256)            // 6144 float4 of weights
#define SMEM_DYN ((3 * 8 * 1024 + Bb * RPAD) * 4)   // 229,888 B

// ---- device scratch (allocation-free rule: __device__ globals) -------------
__device__ __align__(16) float4 g_WT4[256 * 1024];  // Wb [kq][c] for bi_kernel
__device__ __align__(16) float g_Bi[(size_t)Ss * Bb * Hh]; // tanh(x_t W_b^T + b_b)
__device__ __align__(16) float g_h [Bb * Hh];
__device__ __align__(16) float g_hi[Bb * Hh];
__device__ __align__(16) float g_ri[Bb * Hh];
__device__ __align__(128) unsigned g_arrive;
__device__ __align__(128) unsigned g_release;

__global__ void init_kernel() {
    int i = blockIdx.x * blockDim.x + threadIdx.x;
    if (i < Bb * Hh) g_h[i] = 0.0f;
    if (i == 0) { g_arrive = 0u; g_release = 0u; }
}

// ---------------------------------------------------------------------------
// XLA EmitFastTanh, FMA variant (verified bit-exact R8-R13).
__device__ __forceinline__ float xla_tanh(float x) {
    float z = fminf(x, 7.99881172180175781f);
    z = fmaxf(z, -7.99881172180175781f);
    float x2 = __fmul_rn(z, z);
    float p = __fmaf_rn(x2, -2.76076847742355e-16f, 2.00018790482477e-13f);
    p = __fmaf_rn(x2, p, -8.60467152213735e-11f);
    p = __fmaf_rn(x2, p,  5.12229709037114e-08f);
    p = __fmaf_rn(x2, p,  1.48572235717979e-05f);
    p = __fmaf_rn(x2, p,  6.37261928875436e-04f);
    p = __fmaf_rn(x2, p,  4.89352455891786e-03f);
    p = __fmul_rn(z, p);
    float q = __fmaf_rn(x2, 1.19825839466702e-06f, 1.18534705686654e-04f);
    q = __fmaf_rn(x2, q, 2.26843463243900e-03f);
    q = __fmaf_rn(x2, q, 4.89352518554385e-03f);
    return (fabsf(x) < 0.0004f) ? x : __fdiv_rn(p, q);
}

// ---------------------------------------------------------------------------
// Wb transpose into [kq][c] layout for bi_kernel. Pure copy (bit-free).
__global__ void transpose_kernel(const float* __restrict__ Wb) {
    int i = blockIdx.x * blockDim.x + threadIdx.x;   // 0 .. 262143
    if (i >= 262144) return;
    int kq = i >> 10;
    int c  = i & 1023;
    g_WT4[i] = ((const float4*)Wb)[(size_t)c * 256 + kq];
}

// ---------------------------------------------------------------------------
// Bi precompute (verified bit order R8-R13; fp32-FMA-roofline-bound ~0.95 ms).
__global__ __launch_bounds__(NTHR, 1) void bi_kernel(
    const float* __restrict__ x, const float* __restrict__ bbias)
{
    __shared__ float xs[Bb][128];
    const int tid = threadIdx.x;
    const int t   = blockIdx.y;
    const int c   = blockIdx.x * NTHR + tid;
    const float4* wt = g_WT4 + c;                // stride 1024 float4 per kq

    float acc[Bb];
    #pragma unroll
    for (int b = 0; b < Bb; b++) acc[b] = 0.0f;

    for (int kp = 0; kp < 8; kp++) {             // 8 panels of 128 k
        __syncthreads();
        #pragma unroll
        for (int j = 0; j < 4; j++) {
            int i  = tid + j * NTHR;             // 0..1023 float4s
            int b  = i >> 5;
            int kl = i & 31;
            ((float4*)&xs[b][0])[kl] =
                *(const float4*)(x + ((size_t)b * Ss + t) * Hh + kp * 128 + kl * 4);
        }
        __syncthreads();
        #pragma unroll 1
        for (int kl = 0; kl < 32; kl++) {
            float4 w = wt[(kp * 32 + kl) * 1024];
            #pragma unroll
            for (int b = 0; b < Bb; b++) {
                float4 a = *(const float4*)&xs[b][kl * 4];
                acc[b] = __fmaf_rn(a.x, w.x, acc[b]);
                acc[b] = __fmaf_rn(a.y, w.y, acc[b]);
                acc[b] = __fmaf_rn(a.z, w.z, acc[b]);
                acc[b] = __fmaf_rn(a.w, w.w, acc[b]);
            }
        }
    }

    float bias = bbias[c];
    #pragma unroll
    for (int b = 0; b < Bb; b++)
        g_Bi[((size_t)t * Bb + b) * Hh + c] = xla_tanh(__fadd_rn(acc[b], bias));
}

// ---------------------------------------------------------------------------
// Grid barrier (contention-split; verified R10/R13).
__device__ __forceinline__ void gsync(unsigned* epoch) {
    unsigned e = ++(*epoch);
    __syncthreads();
    if (threadIdx.x == 0) {
        __threadfence();
        unsigned a = atomicAdd(&g_arrive, 1u);
        if (a == e * NCTA - 1u) {
            asm volatile("st.release.gpu.u32 [%0], %1;" :: "l"(&g_release), "r"(e));
        }
        unsigned v;
        do {
            asm volatile("ld.acquire.gpu.u32 %0, [%1];" : "=r"(v) : "l"(&g_release));
        } while (v < e);
    }
    __syncthreads();
}

// ---------------------------------------------------------------------------
// Dual-output dot: TWO independent single-accumulator ascending-k chains
// (each bit-identical to the frozen R8 order). ILP=2 keeps FFMA at rt=2 with
// one warp per SMSP; 3 LDS.128 feed 8 FFMA (was 2 LDS per 4 FFMA).
__device__ __forceinline__ void dot2(const float4* __restrict__ wpA,
                                     const float4* __restrict__ wpB,
                                     const float4* __restrict__ ap,
                                     float& zA, float& zB) {
    float a0 = 0.0f, a1 = 0.0f;
    #pragma unroll 8
    for (int kq = 0; kq < 256; kq++) {
        float4 wA = wpA[kq * 8];
        float4 wB = wpB[kq * 8];
        float4 a  = ap[kq];
        a0 = __fmaf_rn(a.x, wA.x, a0);  a1 = __fmaf_rn(a.x, wB.x, a1);
        a0 = __fmaf_rn(a.y, wA.y, a0);  a1 = __fmaf_rn(a.y, wB.y, a1);
        a0 = __fmaf_rn(a.z, wA.z, a0);  a1 = __fmaf_rn(a.z, wB.z, a1);
        a0 = __fmaf_rn(a.w, wA.w, a0);  a1 = __fmaf_rn(a.w, wB.w, a1);
    }
    zA = a0; zB = a1;
}

// Stage all 32 rows of a [32][1024] global vector into padded SMEM (128 thr).
__device__ __forceinline__ void stage(float* __restrict__ s,
                                      const float* __restrict__ src) {
    int tid = threadIdx.x;
    #pragma unroll 8
    for (int j = 0; j < 64; j++) {
        int i  = tid + j * NTS;           // 0..8191 float4s; i = r*256 + kq
        int r  = i >> 8;
        int kq = i & 255;
        *(float4*)(s + r * RPAD + kq * 4) = ((const float4*)src)[i];
    }
}

// Stage fl(ri + pe): single rounded add per element (the reference's literal
// elementwise (ri + p_t)); dot chain order untouched => bit-exact.
__device__ __forceinline__ void stage_add(float* __restrict__ s,
                                          const float* __restrict__ r0,
                                          const float* __restrict__ pe,
                                          int t) {
    int tid = threadIdx.x;
    #pragma unroll 8
    for (int j = 0; j < 64; j++) {
        int i  = tid + j * NTS;
        int r  = i >> 8;
        int kq = i & 255;
        float4 a = ((const float4*)r0)[i];
        float4 q = *(const float4*)(pe + ((size_t)r * Ss + t) * Hh + kq * 4);
        float4 v;
        v.x = __fadd_rn(a.x, q.x); v.y = __fadd_rn(a.y, q.y);
        v.z = __fadd_rn(a.z, q.z); v.w = __fadd_rn(a.w, q.w);
        *(float4*)(s + r * RPAD + kq * 4) = v;
    }
}

// ---------------------------------------------------------------------------
// Sequential recurrence, weight-stationary. CTA cb owns cols [cb*8, cb*8+8)
// x all 32 rows = 256 outputs; 128 threads x 2 outputs (c0+u, c0+u+4).
// Warp w: rows 8w..8w+7 (bl = lane&7), col-pair u = lane>>3.
__global__ __launch_bounds__(NTS, 1) void seq_kernel(
    const float* __restrict__ pe,
    const float* __restrict__ Whb, const float* __restrict__ Wr,
    const float* __restrict__ Wb,
    const float* __restrict__ bb,  const float* __restrict__ bhb,
    const float* __restrict__ br,
    float* __restrict__ out)
{
    extern __shared__ float smem[];
    float4* w_s4  = (float4*)smem;            // [3][256][8] float4 = 96KB
    float*  s_act = smem + 3 * 8 * 1024;      // [32][RPAD]

    const int tid  = threadIdx.x;
    const int lane = tid & 31;
    const int w    = tid >> 5;
    const int c0   = blockIdx.x * 8;
    const int u    = lane >> 3;               // 0..3 (col pair)
    const int bl   = lane & 7;                // 0..7
    const int rl   = w * 8 + bl;              // batch row 0..31
    const int cA   = c0 + u;
    const int cB   = c0 + u + 4;
    const int oA   = rl * Hh + cA;
    const int oB   = rl * Hh + cB;

    // prologue: load this CTA's 8 columns of all three weight matrices.
    for (int idx = tid; idx < W_F4; idx += NTS) {
        int m   = idx >> 11;
        int kq  = (idx >> 3) & 255;
        int cl2 = idx & 7;
        const float* Wm = (m == 0) ? Whb : (m == 1) ? Wr : Wb;
        w_s4[idx] = ((const float4*)Wm)[(size_t)(c0 + cl2) * 256 + kq];
    }
    __syncthreads();

    const float4* wpA_hb = w_s4 + 0 * 2048 + u;
    const float4* wpA_r  = w_s4 + 1 * 2048 + u;
    const float4* wpA_b  = w_s4 + 2 * 2048 + u;
    const float4* ap     = (const float4*)(s_act + rl * RPAD);

    const float bias_hbA = bhb[cA], bias_hbB = bhb[cB];
    const float bias_rA  = br[cA],  bias_rB  = br[cB];
    const float bias_bA  = bb[cA],  bias_bB  = bb[cB];

    unsigned epoch = 0u;
    float hiA = 0.0f, hiB = 0.0f;

    #pragma unroll 1
    for (int t = 0; t < Ss; t++) {
        // sub 1: hi = tanh(h @ W_hb^T + b_hb) + bi[t]
        stage(s_act, g_h);
        float biA = g_Bi[((size_t)t * Bb + rl) * Hh + cA];
        float biB = g_Bi[((size_t)t * Bb + rl) * Hh + cB];
        __syncthreads();
        float zA, zB;
        dot2(wpA_hb, wpA_hb + 4, ap, zA, zB);
        hiA = __fadd_rn(xla_tanh(__fadd_rn(zA, bias_hbA)), biA);
        hiB = __fadd_rn(xla_tanh(__fadd_rn(zB, bias_hbB)), biB);
        g_hi[oA] = hiA; g_hi[oB] = hiB;
        gsync(&epoch);

        // sub 2: ri = tanh(hi @ W_r^T + b_r)
        stage(s_act, g_hi);
        __syncthreads();
        dot2(wpA_r, wpA_r + 4, ap, zA, zB);
        g_ri[oA] = xla_tanh(__fadd_rn(zA, bias_rA));
        g_ri[oB] = xla_tanh(__fadd_rn(zB, bias_rB));
        gsync(&epoch);

        // sub 3: h = hi + tanh((ri + p_t) @ W_b^T + b_b)
        stage_add(s_act, g_ri, pe, t);
        __syncthreads();
        dot2(wpA_b, wpA_b + 4, ap, zA, zB);
        float hnA = __fadd_rn(hiA, xla_tanh(__fadd_rn(zA, bias_bA)));
        float hnB = __fadd_rn(hiB, xla_tanh(__fadd_rn(zB, bias_bB)));
        g_h[oA] = hnA; g_h[oB] = hnB;
        if (t == Ss - 1) { out[oA] = hnA; out[oB] = hnB; }
        gsync(&epoch);
    }
}

// ---------------------------------------------------------------------------
extern "C" void kernel_launch(void* const* d_in, const int* in_sizes, int n_in,
                              void* d_out, int out_size) {
    const float* x   = (const float*)d_in[0];
    const float* pe  = (const float*)d_in[1];
    const float* Wb  = (const float*)d_in[2];
    const float* bb  = (const float*)d_in[3];
    const float* Whb = (const float*)d_in[4];
    const float* bhb = (const float*)d_in[5];
    const float* Wr  = (const float*)d_in[6];
    const float* br  = (const float*)d_in[7];
    float* out = (float*)d_out;

    cudaFuncSetAttribute(seq_kernel, cudaFuncAttributeMaxDynamicSharedMemorySize,
                         SMEM_DYN);

    init_kernel<<<(Bb * Hh + 255) / 256, 256>>>();
    transpose_kernel<<<(262144 + 255) / 256, 256>>>(Wb);
    bi_kernel<<<dim3(Hh / NTHR, Ss), NTHR>>>(x, bb);
    seq_kernel<<<NCTA, NTS, SMEM_DYN>>>(pe, Whb, Wr, Wb, bb, bhb, br, out);
}